// round 6
// baseline (speedup 1.0000x reference)
#include <cuda_runtime.h>
#include <cuda_bf16.h>
#include <cstdint>

// ---------------------------------------------------------------------------
// Transformer forward (B=16,T=512,V=2048,D=512,HD=64,NH=8,L=6,F=2048,MD=16)
// Round 5: TF32x3 tensor-core GEMM (error-compensated split: hi*lo+lo*hi+hi*hi)
// restores fp32-level accuracy while keeping mma.sync throughput.
//   - rel-bias einsums collapse to 17 table rows (causal + clamp(-16,16))
//   - cat=tile(vals,8) @ Wo  ==  vals @ WoSum
//   - scores = Q@K^T as batched GEMM, softmax kernel in-place on d_att
// ---------------------------------------------------------------------------

#define Bsz 16
#define Tq  512
#define Dm  512
#define HDm 64
#define NHm 8
#define Lm  6
#define Fm  2048
#define Vm  2048
#define ROWS (Bsz*Tq)   // 8192

__device__ float d_h   [ROWS * Dm];
__device__ float d_y   [ROWS * Dm];
__device__ float d_q   [ROWS * HDm];
__device__ float d_k   [ROWS * HDm];
__device__ float d_kt  [Bsz * HDm * Tq];
__device__ float d_v   [ROWS * HDm];
__device__ float d_vals[ROWS * HDm];
__device__ float d_att [Bsz * Tq * Tq];
__device__ float d_attA[ROWS * 17];
__device__ float d_ffn [ROWS * Fm];
__device__ float d_ws  [Lm * HDm * Dm];

// ---------------------------------------------------------------------------
// helpers
// ---------------------------------------------------------------------------
__device__ __forceinline__ void cp16(void* s, const void* g) {
    uint32_t sa = (uint32_t)__cvta_generic_to_shared(s);
    asm volatile("cp.async.cg.shared.global [%0], [%1], 16;" :: "r"(sa), "l"(g));
}
__device__ __forceinline__ void cp_commit() {
    asm volatile("cp.async.commit_group;");
}
__device__ __forceinline__ uint32_t f2tf(float x) {
    uint32_t r;
    asm("cvt.rna.tf32.f32 %0, %1;" : "=r"(r) : "f"(x));
    return r;
}
// split v = hi + lo, both tf32-representable
__device__ __forceinline__ void tfsplit(float v, uint32_t& hi, uint32_t& lo) {
    hi = f2tf(v);
    lo = f2tf(v - __uint_as_float(hi));
}
__device__ __forceinline__ void mma_tf32(float* d, const uint32_t* a, const uint32_t* b) {
    asm volatile(
        "mma.sync.aligned.m16n8k8.row.col.f32.tf32.tf32.f32 "
        "{%0,%1,%2,%3}, {%4,%5,%6,%7}, {%8,%9}, {%0,%1,%2,%3};"
        : "+f"(d[0]), "+f"(d[1]), "+f"(d[2]), "+f"(d[3])
        : "r"(a[0]), "r"(a[1]), "r"(a[2]), "r"(a[3]), "r"(b[0]), "r"(b[1]));
}

// ---------------------------------------------------------------------------
// TF32x3 tensor-core GEMM:
//   C[M,N] (+)= A[M,K] @ B[K,N] (+ bias) (ReLU), batched via blockIdx.z.
//   BM=128, BK=16, BN = 128 or 64. 256 threads (8 warps).
//   Requires: M % 128 == 0, N % BN == 0, K % 16 == 0.
// ---------------------------------------------------------------------------
template<int BN_, bool ADD, bool RELU>
__global__ __launch_bounds__(256) void tgemm_kernel(
    const float* __restrict__ A, const float* __restrict__ Bm,
    const float* __restrict__ bias, float* __restrict__ C,
    int K, int lda, int ldb, int ldc,
    long strideA, long strideB, long strideC)
{
    constexpr int BM_ = 128, BK_ = 16;
    constexpr int AS = BK_ + 4;        // 20 floats: conflict-free frag reads
    constexpr int BS = BN_ + 8;        // 136 / 72: conflict-free frag reads
    constexpr int NWN = BN_ / 32;      // warps along n (4 or 2)
    constexpr int WM  = BM_ / (8 / NWN);  // 64 or 32 rows per warp
    constexpr int MT  = WM / 16;       // m16 tiles per warp (4 or 2)

    __shared__ float As[2][BM_][AS];
    __shared__ float Bs[2][BK_][BS];

    A  += (long)blockIdx.z * strideA;
    Bm += (long)blockIdx.z * strideB;
    C  += (long)blockIdx.z * strideC;

    const int row0 = blockIdx.y * BM_;
    const int col0 = blockIdx.x * BN_;
    const int tid = threadIdx.x, lane = tid & 31, wid = tid >> 5;
    const int wn = wid % NWN, wm = wid / NWN;
    const int g = lane >> 2, tq = lane & 3;

    float acc[MT][4][4];
    #pragma unroll
    for (int mt = 0; mt < MT; mt++)
        #pragma unroll
        for (int nt = 0; nt < 4; nt++)
            #pragma unroll
            for (int i = 0; i < 4; i++) acc[mt][nt][i] = 0.f;

    const int a_r = tid >> 1, a_h = tid & 1;      // 2 threads per A row
    const int b_r = tid >> 4, b_c = tid & 15;     // 16 threads per B row

    auto copyA = [&](int kc, int buf) {
        const float* gp = A + (long)(row0 + a_r) * lda + kc * BK_ + a_h * 8;
        cp16(&As[buf][a_r][a_h * 8],     gp);
        cp16(&As[buf][a_r][a_h * 8 + 4], gp + 4);
    };
    auto copyB = [&](int kc, int buf) {
        const float* gp = Bm + (long)(kc * BK_ + b_r) * ldb + col0 + b_c * 4;
        cp16(&Bs[buf][b_r][b_c * 4], gp);
        if (BN_ == 128) cp16(&Bs[buf][b_r][b_c * 4 + 64], gp + 64);
    };

    const int nk = K / BK_;
    copyA(0, 0); copyB(0, 0);
    cp_commit();

    int buf = 0;
    for (int kc = 0; kc < nk; kc++) {
        if (kc + 1 < nk) {
            copyA(kc + 1, buf ^ 1); copyB(kc + 1, buf ^ 1);
            cp_commit();
            asm volatile("cp.async.wait_group 1;");
        } else {
            asm volatile("cp.async.wait_group 0;");
        }
        __syncthreads();

        #pragma unroll
        for (int ks = 0; ks < BK_; ks += 8) {
            uint32_t ah[MT][4], al[MT][4];
            uint32_t bh[4][2], bl[4][2];
            #pragma unroll
            for (int mt = 0; mt < MT; mt++) {
                int r = wm * WM + mt * 16;
                tfsplit(As[buf][r + g    ][ks + tq    ], ah[mt][0], al[mt][0]);
                tfsplit(As[buf][r + g + 8][ks + tq    ], ah[mt][1], al[mt][1]);
                tfsplit(As[buf][r + g    ][ks + tq + 4], ah[mt][2], al[mt][2]);
                tfsplit(As[buf][r + g + 8][ks + tq + 4], ah[mt][3], al[mt][3]);
            }
            #pragma unroll
            for (int nt = 0; nt < 4; nt++) {
                int c = wn * 32 + nt * 8;
                tfsplit(Bs[buf][ks + tq    ][c + g], bh[nt][0], bl[nt][0]);
                tfsplit(Bs[buf][ks + tq + 4][c + g], bh[nt][1], bl[nt][1]);
            }
            // 3-term compensated product: hi*lo + lo*hi + hi*hi
            #pragma unroll
            for (int mt = 0; mt < MT; mt++)
                #pragma unroll
                for (int nt = 0; nt < 4; nt++) {
                    mma_tf32(acc[mt][nt], ah[mt], bl[nt]);
                    mma_tf32(acc[mt][nt], al[mt], bh[nt]);
                    mma_tf32(acc[mt][nt], ah[mt], bh[nt]);
                }
        }
        __syncthreads();
        buf ^= 1;
    }

    // epilogue: d0:(g,2tq) d1:(g,2tq+1) d2:(g+8,2tq) d3:(g+8,2tq+1)
    #pragma unroll
    for (int mt = 0; mt < MT; mt++) {
        int r0 = row0 + wm * WM + mt * 16 + g;
        #pragma unroll
        for (int nt = 0; nt < 4; nt++) {
            int c0 = col0 + wn * 32 + nt * 8 + tq * 2;
            #pragma unroll
            for (int i = 0; i < 2; i++) {
                #pragma unroll
                for (int j = 0; j < 2; j++) {
                    float v = acc[mt][nt][i * 2 + j];
                    int r = r0 + i * 8, c = c0 + j;
                    if (bias) v += bias[c];
                    if (RELU) v = fmaxf(v, 0.f);
                    long o = (long)r * ldc + c;
                    if (ADD) v += C[o];
                    C[o] = v;
                }
            }
        }
    }
}

// ---------------------------------------------------------------------------
// Embedding + positional encoding: h = 2*emb[idx] + pe  (repo's buggy pe)
// ---------------------------------------------------------------------------
__global__ void embed_kernel(const int* __restrict__ idx,
                             const float* __restrict__ emb,
                             float* __restrict__ h)
{
    int i = blockIdx.x * blockDim.x + threadIdx.x;
    int d = i & (Dm - 1);
    int row = i >> 9;
    int t = row & (Tq - 1);
    int tok = idx[row];
    float x = emb[(long)tok * Dm + d];
    int m = d >> 1;
    float inv = __expf(-(float)m * (9.210340371976184f / 128.0f));
    float ang = (float)t * inv;
    float pe = (d & 1) ? cosf(ang) : sinf(ang);
    h[i] = 2.f * x + pe;
}

// ---------------------------------------------------------------------------
// LayerNorm (biased variance), one block per row of 512
// ---------------------------------------------------------------------------
__global__ __launch_bounds__(256) void ln_kernel(
    const float* __restrict__ x, const float* __restrict__ g,
    const float* __restrict__ be, float* __restrict__ y)
{
    long base = (long)blockIdx.x * Dm;
    int tid = threadIdx.x;
    float v0 = x[base + tid], v1 = x[base + tid + 256];
    float s = v0 + v1;
    float ss = v0 * v0 + v1 * v1;
    __shared__ float rs[8], rss[8], mv[2];
    int lane = tid & 31, warp = tid >> 5;
    #pragma unroll
    for (int off = 16; off; off >>= 1) {
        s  += __shfl_xor_sync(0xffffffffu, s, off);
        ss += __shfl_xor_sync(0xffffffffu, ss, off);
    }
    if (lane == 0) { rs[warp] = s; rss[warp] = ss; }
    __syncthreads();
    if (tid == 0) {
        float S = 0.f, SS = 0.f;
        #pragma unroll
        for (int w = 0; w < 8; w++) { S += rs[w]; SS += rss[w]; }
        float mean = S * (1.f / Dm);
        float var  = SS * (1.f / Dm) - mean * mean;
        mv[0] = mean; mv[1] = rsqrtf(var + 1e-5f);
    }
    __syncthreads();
    float mean = mv[0], inv = mv[1];
    y[base + tid]       = (v0 - mean) * inv * g[tid]       + be[tid];
    y[base + tid + 256] = (v1 - mean) * inv * g[tid + 256] + be[tid + 256];
}

// ---------------------------------------------------------------------------
// WoSum[l][h][d] = sum_n Wo[l][n*64+h][d]
// ---------------------------------------------------------------------------
__global__ void wosum_kernel(const float* __restrict__ Wo, float* __restrict__ ws)
{
    int i = blockIdx.x * blockDim.x + threadIdx.x;
    if (i >= Lm * HDm * Dm) return;
    int d = i & (Dm - 1);
    int h = (i >> 9) & (HDm - 1);
    int l = i >> 15;
    float s = 0.f;
    #pragma unroll
    for (int n = 0; n < NHm; n++)
        s += Wo[((long)l * (NHm * HDm) + n * HDm + h) * Dm + d];
    ws[i] = s;
}

// ---------------------------------------------------------------------------
// K transpose: kt[b][h][s] = k[(b*T+s)][h]   (tiled, conflict-free)
// ---------------------------------------------------------------------------
__global__ void kt_kernel(const float* __restrict__ kin, float* __restrict__ kt)
{
    __shared__ float tile[32][33];
    int b = blockIdx.z;
    int s0 = blockIdx.x * 32, h0 = blockIdx.y * 32;
    int x = threadIdx.x;
    for (int y = threadIdx.y; y < 32; y += 8)
        tile[y][x] = kin[((long)(b * Tq + s0 + y)) * HDm + h0 + x];
    __syncthreads();
    for (int y = threadIdx.y; y < 32; y += 8)
        kt[((long)b * HDm + h0 + y) * Tq + s0 + x] = tile[x][y];
}

// ---------------------------------------------------------------------------
// Softmax + rel-bias + bucket sums on precomputed scores (in-place on att).
// One block (256 thr) per (b,t).
// ---------------------------------------------------------------------------
__global__ __launch_bounds__(256) void softmax_kernel(
    const float* __restrict__ Q, float* __restrict__ att,
    const float* __restrict__ tbl, float* __restrict__ attA)
{
    const int row = blockIdx.x;          // b*T + t
    const int b = row >> 9, t = row & (Tq - 1);
    const int tid = threadIdx.x, lane = tid & 31, warp = tid >> 5;

    __shared__ float qs[HDm];
    __shared__ float qrel[17];
    __shared__ float srow[Tq];
    __shared__ float red[8];

    if (tid < HDm) qs[tid] = Q[(long)row * HDm + tid];
    __syncthreads();
    if (tid < 17) {
        const float* tb = tbl + tid * HDm;
        float s = 0.f;
        #pragma unroll
        for (int hh = 0; hh < HDm; hh++) s += qs[hh] * tb[hh];
        qrel[tid] = s;
    }
    __syncthreads();

    const float scale = 0.125f;
    float* arow = att + ((long)b * Tq + t) * Tq;
    for (int s = tid; s <= t; s += 256) {
        int dm = s - t + 16; if (dm < 0) dm = 0;
        srow[s] = (arow[s] + qrel[dm]) * scale;
    }
    __syncthreads();

    float m = -1e30f;
    for (int s = tid; s <= t; s += 256) m = fmaxf(m, srow[s]);
    #pragma unroll
    for (int off = 16; off; off >>= 1)
        m = fmaxf(m, __shfl_xor_sync(0xffffffffu, m, off));
    if (lane == 0) red[warp] = m;
    __syncthreads();
    if (tid == 0) {
        float mm = red[0];
        #pragma unroll
        for (int w = 1; w < 8; w++) mm = fmaxf(mm, red[w]);
        red[0] = mm;
    }
    __syncthreads();
    m = red[0];
    __syncthreads();

    float sum = 0.f;
    for (int s = tid; s < Tq; s += 256) {
        float e = (s <= t) ? __expf(srow[s] - m) : 0.f;
        srow[s] = e;
        sum += e;
    }
    #pragma unroll
    for (int off = 16; off; off >>= 1)
        sum += __shfl_xor_sync(0xffffffffu, sum, off);
    if (lane == 0) red[warp] = sum;
    __syncthreads();
    if (tid == 0) {
        float ss = 0.f;
        #pragma unroll
        for (int w = 0; w < 8; w++) ss += red[w];
        red[0] = ss;
    }
    __syncthreads();
    float inv = 1.f / red[0];
    __syncthreads();

    for (int s = tid; s < Tq; s += 256) arow[s] = srow[s] * inv;

    float a0 = 0.f;
    for (int s = tid; s < Tq; s += 256)
        if (s <= t - 16) a0 += srow[s];
    #pragma unroll
    for (int off = 16; off; off >>= 1)
        a0 += __shfl_xor_sync(0xffffffffu, a0, off);
    if (lane == 0) red[warp] = a0;
    __syncthreads();
    if (tid == 0) {
        float ss = 0.f;
        #pragma unroll
        for (int w = 0; w < 8; w++) ss += red[w];
        attA[(long)row * 17 + 0] = ss * inv;
    }
    if (tid >= 1 && tid <= 16) {
        int s = t - 16 + tid;
        attA[(long)row * 17 + tid] = (s >= 0) ? srow[s] * inv : 0.f;
    }
}

// ---------------------------------------------------------------------------
// vals[row,h] += sum_{j<17} attA[row,j] * tbl[j,h]
// ---------------------------------------------------------------------------
__global__ __launch_bounds__(64) void valbias_kernel(
    float* __restrict__ vals, const float* __restrict__ attA,
    const float* __restrict__ tbl)
{
    int row = blockIdx.x;
    int hh = threadIdx.x;
    __shared__ float aa[17];
    if (hh < 17) aa[hh] = attA[(long)row * 17 + hh];
    __syncthreads();
    float v = vals[(long)row * HDm + hh];
    #pragma unroll
    for (int j = 0; j < 17; j++) v += aa[j] * tbl[j * HDm + hh];
    vals[(long)row * HDm + hh] = v;
}

// ---------------------------------------------------------------------------
extern "C" void kernel_launch(void* const* d_in, const int* in_sizes, int n_in,
                              void* d_out, int out_size)
{
    const int*   idx  = (const int*)  d_in[0];
    const float* emb  = (const float*)d_in[1];
    const float* Wq   = (const float*)d_in[2];
    const float* bq   = (const float*)d_in[3];
    const float* Wk   = (const float*)d_in[4];
    const float* bk   = (const float*)d_in[5];
    const float* Wv   = (const float*)d_in[6];
    const float* bv   = (const float*)d_in[7];
    const float* rel  = (const float*)d_in[8];
    const float* Wo   = (const float*)d_in[9];
    const float* bo   = (const float*)d_in[10];
    const float* g1   = (const float*)d_in[11];
    const float* be1  = (const float*)d_in[12];
    const float* g2   = (const float*)d_in[13];
    const float* be2  = (const float*)d_in[14];
    const float* W1   = (const float*)d_in[15];
    const float* b1   = (const float*)d_in[16];
    const float* W2   = (const float*)d_in[17];
    const float* b2   = (const float*)d_in[18];
    const float* Wout = (const float*)d_in[19];
    const float* bout = (const float*)d_in[20];
    float* out = (float*)d_out;

    float *h, *y, *q, *k, *kt, *v, *vals, *att, *attA, *ffn, *ws;
    cudaGetSymbolAddress((void**)&h,    d_h);
    cudaGetSymbolAddress((void**)&y,    d_y);
    cudaGetSymbolAddress((void**)&q,    d_q);
    cudaGetSymbolAddress((void**)&k,    d_k);
    cudaGetSymbolAddress((void**)&kt,   d_kt);
    cudaGetSymbolAddress((void**)&v,    d_v);
    cudaGetSymbolAddress((void**)&vals, d_vals);
    cudaGetSymbolAddress((void**)&att,  d_att);
    cudaGetSymbolAddress((void**)&attA, d_attA);
    cudaGetSymbolAddress((void**)&ffn,  d_ffn);
    cudaGetSymbolAddress((void**)&ws,   d_ws);

    embed_kernel<<<ROWS * Dm / 256, 256>>>(idx, emb, h);
    wosum_kernel<<<(Lm * HDm * Dm + 255) / 256, 256>>>(Wo, ws);

    for (int l = 0; l < Lm; l++) {
        const float* tbl = rel + (long)l * 33 * HDm;

        ln_kernel<<<ROWS, 256>>>(h, g1 + l * Dm, be1 + l * Dm, y);

        // Q, K, V projections: [8192,512] x [512,64]  (BN=64)
        {
            dim3 grid(1, ROWS / 128, 1);
            tgemm_kernel<64, false, false><<<grid, 256>>>(
                y, Wq + (long)l * Dm * HDm, bq + l * HDm, q,
                Dm, Dm, HDm, HDm, 0, 0, 0);
            tgemm_kernel<64, false, false><<<grid, 256>>>(
                y, Wk + (long)l * Dm * HDm, bk + l * HDm, k,
                Dm, Dm, HDm, HDm, 0, 0, 0);
            tgemm_kernel<64, false, false><<<grid, 256>>>(
                y, Wv + (long)l * Dm * HDm, bv + l * HDm, v,
                Dm, Dm, HDm, HDm, 0, 0, 0);
        }

        // K transpose for scores GEMM
        {
            dim3 grid(Tq / 32, HDm / 32, Bsz);
            kt_kernel<<<grid, dim3(32, 8)>>>(k, kt);
        }

        // scores = Q @ K^T : batched [512,64] x [64,512] -> att
        {
            dim3 grid(Tq / 128, Tq / 128, Bsz);
            tgemm_kernel<128, false, false><<<grid, 256>>>(
                q, kt, nullptr, att,
                HDm, HDm, Tq, Tq,
                (long)Tq * HDm, (long)HDm * Tq, (long)Tq * Tq);
        }

        softmax_kernel<<<ROWS, 256>>>(q, att, tbl, attA);

        // vals = att @ V : batched [512,512] x [512,64]  (BN=64)
        {
            dim3 grid(1, Tq / 128, Bsz);
            tgemm_kernel<64, false, false><<<grid, 256>>>(
                att, v, nullptr, vals,
                Tq, Tq, HDm, HDm,
                (long)Tq * Tq, (long)Tq * HDm, (long)Tq * HDm);
        }

        valbias_kernel<<<ROWS, 64>>>(vals, attA, tbl);

        // h += vals @ WoSum[l] + bo[l] : [8192,64] x [64,512]
        {
            dim3 grid(Dm / 128, ROWS / 128, 1);
            tgemm_kernel<128, true, false><<<grid, 256>>>(
                vals, ws + (long)l * HDm * Dm, bo + l * Dm, h,
                HDm, HDm, Dm, Dm, 0, 0, 0);
        }

        ln_kernel<<<ROWS, 256>>>(h, g2 + l * Dm, be2 + l * Dm, y);

        // ffn = relu(y @ W1 + b1) : [8192,512] x [512,2048]
        {
            dim3 grid(Fm / 128, ROWS / 128, 1);
            tgemm_kernel<128, false, true><<<grid, 256>>>(
                y, W1 + (long)l * Dm * Fm, b1 + l * Fm, ffn,
                Dm, Dm, Fm, Fm, 0, 0, 0);
        }

        // h += ffn @ W2 + b2 : [8192,2048] x [2048,512]
        {
            dim3 grid(Dm / 128, ROWS / 128, 1);
            tgemm_kernel<128, true, false><<<grid, 256>>>(
                ffn, W2 + (long)l * Fm * Dm, b2 + l * Dm, h,
                Fm, Fm, Dm, Dm, 0, 0, 0);
        }
    }

    // logits = h @ Wout + bout : [8192,512] x [512,2048]
    {
        dim3 grid(Vm / 128, ROWS / 128, 1);
        tgemm_kernel<128, false, false><<<grid, 256>>>(
            h, Wout, bout, out,
            Dm, Dm, Vm, Vm, 0, 0, 0);
    }
}

// round 7
// speedup vs baseline: 1.0010x; 1.0010x over previous
#include <cuda_runtime.h>
#include <cuda_bf16.h>
#include <cstdint>

// ---------------------------------------------------------------------------
// Transformer forward (B=16,T=512,V=2048,D=512,HD=64,NH=8,L=6,F=2048,MD=16)
// Round 5: TF32x3 tensor-core GEMM (error-compensated split: hi*lo+lo*hi+hi*hi)
// restores fp32-level accuracy while keeping mma.sync throughput.
//   - rel-bias einsums collapse to 17 table rows (causal + clamp(-16,16))
//   - cat=tile(vals,8) @ Wo  ==  vals @ WoSum
//   - scores = Q@K^T as batched GEMM, softmax kernel in-place on d_att
// ---------------------------------------------------------------------------

#define Bsz 16
#define Tq  512
#define Dm  512
#define HDm 64
#define NHm 8
#define Lm  6
#define Fm  2048
#define Vm  2048
#define ROWS (Bsz*Tq)   // 8192

__device__ float d_h   [ROWS * Dm];
__device__ float d_y   [ROWS * Dm];
__device__ float d_q   [ROWS * HDm];
__device__ float d_k   [ROWS * HDm];
__device__ float d_kt  [Bsz * HDm * Tq];
__device__ float d_v   [ROWS * HDm];
__device__ float d_vals[ROWS * HDm];
__device__ float d_att [Bsz * Tq * Tq];
__device__ float d_attA[ROWS * 17];
__device__ float d_ffn [ROWS * Fm];
__device__ float d_ws  [Lm * HDm * Dm];

// ---------------------------------------------------------------------------
// helpers
// ---------------------------------------------------------------------------
__device__ __forceinline__ void cp16(void* s, const void* g) {
    uint32_t sa = (uint32_t)__cvta_generic_to_shared(s);
    asm volatile("cp.async.cg.shared.global [%0], [%1], 16;" :: "r"(sa), "l"(g));
}
__device__ __forceinline__ void cp_commit() {
    asm volatile("cp.async.commit_group;");
}
__device__ __forceinline__ uint32_t f2tf(float x) {
    uint32_t r;
    asm("cvt.rna.tf32.f32 %0, %1;" : "=r"(r) : "f"(x));
    return r;
}
// split v = hi + lo, both tf32-representable
__device__ __forceinline__ void tfsplit(float v, uint32_t& hi, uint32_t& lo) {
    hi = f2tf(v);
    lo = f2tf(v - __uint_as_float(hi));
}
__device__ __forceinline__ void mma_tf32(float* d, const uint32_t* a, const uint32_t* b) {
    asm volatile(
        "mma.sync.aligned.m16n8k8.row.col.f32.tf32.tf32.f32 "
        "{%0,%1,%2,%3}, {%4,%5,%6,%7}, {%8,%9}, {%0,%1,%2,%3};"
        : "+f"(d[0]), "+f"(d[1]), "+f"(d[2]), "+f"(d[3])
        : "r"(a[0]), "r"(a[1]), "r"(a[2]), "r"(a[3]), "r"(b[0]), "r"(b[1]));
}

// ---------------------------------------------------------------------------
// TF32x3 tensor-core GEMM:
//   C[M,N] (+)= A[M,K] @ B[K,N] (+ bias) (ReLU), batched via blockIdx.z.
//   BM=128, BK=16, BN = 128 or 64. 256 threads (8 warps).
//   Requires: M % 128 == 0, N % BN == 0, K % 16 == 0.
// ---------------------------------------------------------------------------
template<int BN_, bool ADD, bool RELU>
__global__ __launch_bounds__(256) void tgemm_kernel(
    const float* __restrict__ A, const float* __restrict__ Bm,
    const float* __restrict__ bias, float* __restrict__ C,
    int K, int lda, int ldb, int ldc,
    long strideA, long strideB, long strideC)
{
    constexpr int BM_ = 128, BK_ = 16;
    constexpr int AS = BK_ + 4;        // 20 floats: conflict-free frag reads
    constexpr int BS = BN_ + 8;        // 136 / 72: conflict-free frag reads
    constexpr int NWN = BN_ / 32;      // warps along n (4 or 2)
    constexpr int WM  = BM_ / (8 / NWN);  // 64 or 32 rows per warp
    constexpr int MT  = WM / 16;       // m16 tiles per warp (4 or 2)

    __shared__ float As[2][BM_][AS];
    __shared__ float Bs[2][BK_][BS];

    A  += (long)blockIdx.z * strideA;
    Bm += (long)blockIdx.z * strideB;
    C  += (long)blockIdx.z * strideC;

    const int row0 = blockIdx.y * BM_;
    const int col0 = blockIdx.x * BN_;
    const int tid = threadIdx.x, lane = tid & 31, wid = tid >> 5;
    const int wn = wid % NWN, wm = wid / NWN;
    const int g = lane >> 2, tq = lane & 3;

    float acc[MT][4][4];
    #pragma unroll
    for (int mt = 0; mt < MT; mt++)
        #pragma unroll
        for (int nt = 0; nt < 4; nt++)
            #pragma unroll
            for (int i = 0; i < 4; i++) acc[mt][nt][i] = 0.f;

    const int a_r = tid >> 1, a_h = tid & 1;      // 2 threads per A row
    const int b_r = tid >> 4, b_c = tid & 15;     // 16 threads per B row

    auto copyA = [&](int kc, int buf) {
        const float* gp = A + (long)(row0 + a_r) * lda + kc * BK_ + a_h * 8;
        cp16(&As[buf][a_r][a_h * 8],     gp);
        cp16(&As[buf][a_r][a_h * 8 + 4], gp + 4);
    };
    auto copyB = [&](int kc, int buf) {
        const float* gp = Bm + (long)(kc * BK_ + b_r) * ldb + col0 + b_c * 4;
        cp16(&Bs[buf][b_r][b_c * 4], gp);
        if (BN_ == 128) cp16(&Bs[buf][b_r][b_c * 4 + 64], gp + 64);
    };

    const int nk = K / BK_;
    copyA(0, 0); copyB(0, 0);
    cp_commit();

    int buf = 0;
    for (int kc = 0; kc < nk; kc++) {
        if (kc + 1 < nk) {
            copyA(kc + 1, buf ^ 1); copyB(kc + 1, buf ^ 1);
            cp_commit();
            asm volatile("cp.async.wait_group 1;");
        } else {
            asm volatile("cp.async.wait_group 0;");
        }
        __syncthreads();

        #pragma unroll
        for (int ks = 0; ks < BK_; ks += 8) {
            uint32_t ah[MT][4], al[MT][4];
            uint32_t bh[4][2], bl[4][2];
            #pragma unroll
            for (int mt = 0; mt < MT; mt++) {
                int r = wm * WM + mt * 16;
                tfsplit(As[buf][r + g    ][ks + tq    ], ah[mt][0], al[mt][0]);
                tfsplit(As[buf][r + g + 8][ks + tq    ], ah[mt][1], al[mt][1]);
                tfsplit(As[buf][r + g    ][ks + tq + 4], ah[mt][2], al[mt][2]);
                tfsplit(As[buf][r + g + 8][ks + tq + 4], ah[mt][3], al[mt][3]);
            }
            #pragma unroll
            for (int nt = 0; nt < 4; nt++) {
                int c = wn * 32 + nt * 8;
                tfsplit(Bs[buf][ks + tq    ][c + g], bh[nt][0], bl[nt][0]);
                tfsplit(Bs[buf][ks + tq + 4][c + g], bh[nt][1], bl[nt][1]);
            }
            // 3-term compensated product: hi*lo + lo*hi + hi*hi
            #pragma unroll
            for (int mt = 0; mt < MT; mt++)
                #pragma unroll
                for (int nt = 0; nt < 4; nt++) {
                    mma_tf32(acc[mt][nt], ah[mt], bl[nt]);
                    mma_tf32(acc[mt][nt], al[mt], bh[nt]);
                    mma_tf32(acc[mt][nt], ah[mt], bh[nt]);
                }
        }
        __syncthreads();
        buf ^= 1;
    }

    // epilogue: d0:(g,2tq) d1:(g,2tq+1) d2:(g+8,2tq) d3:(g+8,2tq+1)
    #pragma unroll
    for (int mt = 0; mt < MT; mt++) {
        int r0 = row0 + wm * WM + mt * 16 + g;
        #pragma unroll
        for (int nt = 0; nt < 4; nt++) {
            int c0 = col0 + wn * 32 + nt * 8 + tq * 2;
            #pragma unroll
            for (int i = 0; i < 2; i++) {
                #pragma unroll
                for (int j = 0; j < 2; j++) {
                    float v = acc[mt][nt][i * 2 + j];
                    int r = r0 + i * 8, c = c0 + j;
                    if (bias) v += bias[c];
                    if (RELU) v = fmaxf(v, 0.f);
                    long o = (long)r * ldc + c;
                    if (ADD) v += C[o];
                    C[o] = v;
                }
            }
        }
    }
}

// ---------------------------------------------------------------------------
// Embedding + positional encoding: h = 2*emb[idx] + pe  (repo's buggy pe)
// ---------------------------------------------------------------------------
__global__ void embed_kernel(const int* __restrict__ idx,
                             const float* __restrict__ emb,
                             float* __restrict__ h)
{
    int i = blockIdx.x * blockDim.x + threadIdx.x;
    int d = i & (Dm - 1);
    int row = i >> 9;
    int t = row & (Tq - 1);
    int tok = idx[row];
    float x = emb[(long)tok * Dm + d];
    int m = d >> 1;
    float inv = __expf(-(float)m * (9.210340371976184f / 128.0f));
    float ang = (float)t * inv;
    float pe = (d & 1) ? cosf(ang) : sinf(ang);
    h[i] = 2.f * x + pe;
}

// ---------------------------------------------------------------------------
// LayerNorm (biased variance), one block per row of 512
// ---------------------------------------------------------------------------
__global__ __launch_bounds__(256) void ln_kernel(
    const float* __restrict__ x, const float* __restrict__ g,
    const float* __restrict__ be, float* __restrict__ y)
{
    long base = (long)blockIdx.x * Dm;
    int tid = threadIdx.x;
    float v0 = x[base + tid], v1 = x[base + tid + 256];
    float s = v0 + v1;
    float ss = v0 * v0 + v1 * v1;
    __shared__ float rs[8], rss[8], mv[2];
    int lane = tid & 31, warp = tid >> 5;
    #pragma unroll
    for (int off = 16; off; off >>= 1) {
        s  += __shfl_xor_sync(0xffffffffu, s, off);
        ss += __shfl_xor_sync(0xffffffffu, ss, off);
    }
    if (lane == 0) { rs[warp] = s; rss[warp] = ss; }
    __syncthreads();
    if (tid == 0) {
        float S = 0.f, SS = 0.f;
        #pragma unroll
        for (int w = 0; w < 8; w++) { S += rs[w]; SS += rss[w]; }
        float mean = S * (1.f / Dm);
        float var  = SS * (1.f / Dm) - mean * mean;
        mv[0] = mean; mv[1] = rsqrtf(var + 1e-5f);
    }
    __syncthreads();
    float mean = mv[0], inv = mv[1];
    y[base + tid]       = (v0 - mean) * inv * g[tid]       + be[tid];
    y[base + tid + 256] = (v1 - mean) * inv * g[tid + 256] + be[tid + 256];
}

// ---------------------------------------------------------------------------
// WoSum[l][h][d] = sum_n Wo[l][n*64+h][d]
// ---------------------------------------------------------------------------
__global__ void wosum_kernel(const float* __restrict__ Wo, float* __restrict__ ws)
{
    int i = blockIdx.x * blockDim.x + threadIdx.x;
    if (i >= Lm * HDm * Dm) return;
    int d = i & (Dm - 1);
    int h = (i >> 9) & (HDm - 1);
    int l = i >> 15;
    float s = 0.f;
    #pragma unroll
    for (int n = 0; n < NHm; n++)
        s += Wo[((long)l * (NHm * HDm) + n * HDm + h) * Dm + d];
    ws[i] = s;
}

// ---------------------------------------------------------------------------
// K transpose: kt[b][h][s] = k[(b*T+s)][h]   (tiled, conflict-free)
// ---------------------------------------------------------------------------
__global__ void kt_kernel(const float* __restrict__ kin, float* __restrict__ kt)
{
    __shared__ float tile[32][33];
    int b = blockIdx.z;
    int s0 = blockIdx.x * 32, h0 = blockIdx.y * 32;
    int x = threadIdx.x;
    for (int y = threadIdx.y; y < 32; y += 8)
        tile[y][x] = kin[((long)(b * Tq + s0 + y)) * HDm + h0 + x];
    __syncthreads();
    for (int y = threadIdx.y; y < 32; y += 8)
        kt[((long)b * HDm + h0 + y) * Tq + s0 + x] = tile[x][y];
}

// ---------------------------------------------------------------------------
// Softmax + rel-bias + bucket sums on precomputed scores (in-place on att).
// One block (256 thr) per (b,t).
// ---------------------------------------------------------------------------
__global__ __launch_bounds__(256) void softmax_kernel(
    const float* __restrict__ Q, float* __restrict__ att,
    const float* __restrict__ tbl, float* __restrict__ attA)
{
    const int row = blockIdx.x;          // b*T + t
    const int b = row >> 9, t = row & (Tq - 1);
    const int tid = threadIdx.x, lane = tid & 31, warp = tid >> 5;

    __shared__ float qs[HDm];
    __shared__ float qrel[17];
    __shared__ float srow[Tq];
    __shared__ float red[8];

    if (tid < HDm) qs[tid] = Q[(long)row * HDm + tid];
    __syncthreads();
    if (tid < 17) {
        const float* tb = tbl + tid * HDm;
        float s = 0.f;
        #pragma unroll
        for (int hh = 0; hh < HDm; hh++) s += qs[hh] * tb[hh];
        qrel[tid] = s;
    }
    __syncthreads();

    const float scale = 0.125f;
    float* arow = att + ((long)b * Tq + t) * Tq;
    for (int s = tid; s <= t; s += 256) {
        int dm = s - t + 16; if (dm < 0) dm = 0;
        srow[s] = (arow[s] + qrel[dm]) * scale;
    }
    __syncthreads();

    float m = -1e30f;
    for (int s = tid; s <= t; s += 256) m = fmaxf(m, srow[s]);
    #pragma unroll
    for (int off = 16; off; off >>= 1)
        m = fmaxf(m, __shfl_xor_sync(0xffffffffu, m, off));
    if (lane == 0) red[warp] = m;
    __syncthreads();
    if (tid == 0) {
        float mm = red[0];
        #pragma unroll
        for (int w = 1; w < 8; w++) mm = fmaxf(mm, red[w]);
        red[0] = mm;
    }
    __syncthreads();
    m = red[0];
    __syncthreads();

    float sum = 0.f;
    for (int s = tid; s < Tq; s += 256) {
        float e = (s <= t) ? __expf(srow[s] - m) : 0.f;
        srow[s] = e;
        sum += e;
    }
    #pragma unroll
    for (int off = 16; off; off >>= 1)
        sum += __shfl_xor_sync(0xffffffffu, sum, off);
    if (lane == 0) red[warp] = sum;
    __syncthreads();
    if (tid == 0) {
        float ss = 0.f;
        #pragma unroll
        for (int w = 0; w < 8; w++) ss += red[w];
        red[0] = ss;
    }
    __syncthreads();
    float inv = 1.f / red[0];
    __syncthreads();

    for (int s = tid; s < Tq; s += 256) arow[s] = srow[s] * inv;

    float a0 = 0.f;
    for (int s = tid; s < Tq; s += 256)
        if (s <= t - 16) a0 += srow[s];
    #pragma unroll
    for (int off = 16; off; off >>= 1)
        a0 += __shfl_xor_sync(0xffffffffu, a0, off);
    if (lane == 0) red[warp] = a0;
    __syncthreads();
    if (tid == 0) {
        float ss = 0.f;
        #pragma unroll
        for (int w = 0; w < 8; w++) ss += red[w];
        attA[(long)row * 17 + 0] = ss * inv;
    }
    if (tid >= 1 && tid <= 16) {
        int s = t - 16 + tid;
        attA[(long)row * 17 + tid] = (s >= 0) ? srow[s] * inv : 0.f;
    }
}

// ---------------------------------------------------------------------------
// vals[row,h] += sum_{j<17} attA[row,j] * tbl[j,h]
// ---------------------------------------------------------------------------
__global__ __launch_bounds__(64) void valbias_kernel(
    float* __restrict__ vals, const float* __restrict__ attA,
    const float* __restrict__ tbl)
{
    int row = blockIdx.x;
    int hh = threadIdx.x;
    __shared__ float aa[17];
    if (hh < 17) aa[hh] = attA[(long)row * 17 + hh];
    __syncthreads();
    float v = vals[(long)row * HDm + hh];
    #pragma unroll
    for (int j = 0; j < 17; j++) v += aa[j] * tbl[j * HDm + hh];
    vals[(long)row * HDm + hh] = v;
}

// ---------------------------------------------------------------------------
extern "C" void kernel_launch(void* const* d_in, const int* in_sizes, int n_in,
                              void* d_out, int out_size)
{
    const int*   idx  = (const int*)  d_in[0];
    const float* emb  = (const float*)d_in[1];
    const float* Wq   = (const float*)d_in[2];
    const float* bq   = (const float*)d_in[3];
    const float* Wk   = (const float*)d_in[4];
    const float* bk   = (const float*)d_in[5];
    const float* Wv   = (const float*)d_in[6];
    const float* bv   = (const float*)d_in[7];
    const float* rel  = (const float*)d_in[8];
    const float* Wo   = (const float*)d_in[9];
    const float* bo   = (const float*)d_in[10];
    const float* g1   = (const float*)d_in[11];
    const float* be1  = (const float*)d_in[12];
    const float* g2   = (const float*)d_in[13];
    const float* be2  = (const float*)d_in[14];
    const float* W1   = (const float*)d_in[15];
    const float* b1   = (const float*)d_in[16];
    const float* W2   = (const float*)d_in[17];
    const float* b2   = (const float*)d_in[18];
    const float* Wout = (const float*)d_in[19];
    const float* bout = (const float*)d_in[20];
    float* out = (float*)d_out;

    float *h, *y, *q, *k, *kt, *v, *vals, *att, *attA, *ffn, *ws;
    cudaGetSymbolAddress((void**)&h,    d_h);
    cudaGetSymbolAddress((void**)&y,    d_y);
    cudaGetSymbolAddress((void**)&q,    d_q);
    cudaGetSymbolAddress((void**)&k,    d_k);
    cudaGetSymbolAddress((void**)&kt,   d_kt);
    cudaGetSymbolAddress((void**)&v,    d_v);
    cudaGetSymbolAddress((void**)&vals, d_vals);
    cudaGetSymbolAddress((void**)&att,  d_att);
    cudaGetSymbolAddress((void**)&attA, d_attA);
    cudaGetSymbolAddress((void**)&ffn,  d_ffn);
    cudaGetSymbolAddress((void**)&ws,   d_ws);

    embed_kernel<<<ROWS * Dm / 256, 256>>>(idx, emb, h);
    wosum_kernel<<<(Lm * HDm * Dm + 255) / 256, 256>>>(Wo, ws);

    for (int l = 0; l < Lm; l++) {
        const float* tbl = rel + (long)l * 33 * HDm;

        ln_kernel<<<ROWS, 256>>>(h, g1 + l * Dm, be1 + l * Dm, y);

        // Q, K, V projections: [8192,512] x [512,64]  (BN=64)
        {
            dim3 grid(1, ROWS / 128, 1);
            tgemm_kernel<64, false, false><<<grid, 256>>>(
                y, Wq + (long)l * Dm * HDm, bq + l * HDm, q,
                Dm, Dm, HDm, HDm, 0, 0, 0);
            tgemm_kernel<64, false, false><<<grid, 256>>>(
                y, Wk + (long)l * Dm * HDm, bk + l * HDm, k,
                Dm, Dm, HDm, HDm, 0, 0, 0);
            tgemm_kernel<64, false, false><<<grid, 256>>>(
                y, Wv + (long)l * Dm * HDm, bv + l * HDm, v,
                Dm, Dm, HDm, HDm, 0, 0, 0);
        }

        // K transpose for scores GEMM
        {
            dim3 grid(Tq / 32, HDm / 32, Bsz);
            kt_kernel<<<grid, dim3(32, 8)>>>(k, kt);
        }

        // scores = Q @ K^T : batched [512,64] x [64,512] -> att
        {
            dim3 grid(Tq / 128, Tq / 128, Bsz);
            tgemm_kernel<128, false, false><<<grid, 256>>>(
                q, kt, nullptr, att,
                HDm, HDm, Tq, Tq,
                (long)Tq * HDm, (long)HDm * Tq, (long)Tq * Tq);
        }

        softmax_kernel<<<ROWS, 256>>>(q, att, tbl, attA);

        // vals = att @ V : batched [512,512] x [512,64]  (BN=64)
        {
            dim3 grid(1, Tq / 128, Bsz);
            tgemm_kernel<64, false, false><<<grid, 256>>>(
                att, v, nullptr, vals,
                Tq, Tq, HDm, HDm,
                (long)Tq * Tq, (long)Tq * HDm, (long)Tq * HDm);
        }

        valbias_kernel<<<ROWS, 64>>>(vals, attA, tbl);

        // h += vals @ WoSum[l] + bo[l] : [8192,64] x [64,512]
        {
            dim3 grid(Dm / 128, ROWS / 128, 1);
            tgemm_kernel<128, true, false><<<grid, 256>>>(
                vals, ws + (long)l * HDm * Dm, bo + l * Dm, h,
                HDm, HDm, Dm, Dm, 0, 0, 0);
        }

        ln_kernel<<<ROWS, 256>>>(h, g2 + l * Dm, be2 + l * Dm, y);

        // ffn = relu(y @ W1 + b1) : [8192,512] x [512,2048]
        {
            dim3 grid(Fm / 128, ROWS / 128, 1);
            tgemm_kernel<128, false, true><<<grid, 256>>>(
                y, W1 + (long)l * Dm * Fm, b1 + l * Fm, ffn,
                Dm, Dm, Fm, Fm, 0, 0, 0);
        }

        // h += ffn @ W2 + b2 : [8192,2048] x [2048,512]
        {
            dim3 grid(Dm / 128, ROWS / 128, 1);
            tgemm_kernel<128, true, false><<<grid, 256>>>(
                ffn, W2 + (long)l * Fm * Dm, b2 + l * Dm, h,
                Fm, Fm, Dm, Dm, 0, 0, 0);
        }
    }

    // logits = h @ Wout + bout : [8192,512] x [512,2048]
    {
        dim3 grid(Vm / 128, ROWS / 128, 1);
        tgemm_kernel<128, false, false><<<grid, 256>>>(
            h, Wout, bout, out,
            Dm, Dm, Vm, Vm, 0, 0, 0);
    }
}